// round 17
// baseline (speedup 1.0000x reference)
#include <cuda_runtime.h>
#include <cuda_bf16.h>
#include <math.h>
#include <stdint.h>

#define T_DIM 1024
#define S_DIM 128
#define H_DIM 512
#define LN_EPS 1e-5f

#define NCHUNKS 24                  // virtual K = 1536 (hi,hi,lo x hi,lo,hi)
#define KCHUNK 64
#define LDS_STRIDE 72
#define A_ELEMS (64 * LDS_STRIDE)

#define PROD_CTAS 144
#define HC 32
#define TT 32
#define CONS_CTAS ((H_DIM / HC) * (T_DIM / TT))   // 512
#define LN_CTAS (T_DIM / 2)                       // 512
#define MTILES 18
#define TTILES (T_DIM / TT)                       // 32

// Scratch (allocation-free rule: __device__ globals)
__device__ float d_gt[T_DIM * H_DIM];
__device__ float d_gs[S_DIM * H_DIM];
__device__ float d_x[T_DIM * H_DIM];              // pre-LN x (deterministic)
__device__ unsigned int d_cnt[MTILES];            // GEMM tile release counters
__device__ unsigned int d_tcnt[TTILES];           // consumer ttile counters

// ---------------------------------------------------------------------------
// PTX helpers
// ---------------------------------------------------------------------------
__device__ __forceinline__ unsigned ld_acq(const unsigned* p) {
    unsigned v;
    asm volatile("ld.acquire.gpu.global.u32 %0, [%1];" : "=r"(v) : "l"(p) : "memory");
    return v;
}
__device__ __forceinline__ void red_release_add(unsigned* p, unsigned v) {
    asm volatile("red.release.gpu.global.add.u32 [%0], %1;" :: "l"(p), "r"(v) : "memory");
}
__device__ __forceinline__ uint32_t bfpack2(float a, float b) {
    __nv_bfloat162 t = __floats2bfloat162_rn(a, b);
    return *reinterpret_cast<uint32_t*>(&t);
}
__device__ __forceinline__ float bflo(float x) {
    return x - __bfloat162float(__float2bfloat16(x));
}

// virtual chunk -> element offset in [hi(512), lo(512)] space
// A sections: [hi, hi, lo];  W sections: [hi, lo, hi]
__device__ __forceinline__ int chunk_off_A(int c) {
    return (c < 8) ? c * 64 : (c < 16) ? (c - 8) * 64 : 512 + (c - 16) * 64;
}
__device__ __forceinline__ int chunk_off_W(int c) {
    return (c < 8) ? c * 64 : (c < 16) ? 512 + (c - 8) * 64 : (c - 16) * 64;
}

// ---------------------------------------------------------------------------
// ONE kernel: producers (GEMM, on-the-fly fp32->split-bf16), consumers
// (gates + enrichment), layernorm (tail, counter-gated).
// ---------------------------------------------------------------------------
__global__ __launch_bounds__(256, 2) void merged_kernel(
    const float* __restrict__ text,
    const float* __restrict__ sstruct,
    const int*   __restrict__ mask,
    const float* __restrict__ gate_w,
    const float* __restrict__ gate_b,
    const float* __restrict__ gamma,
    const float* __restrict__ beta,
    float* __restrict__ enriched,
    float* __restrict__ gates)
{
    __shared__ __align__(16) unsigned char sbuf[32768];
    __shared__ float lnred[2][2][4];

    const int bx  = blockIdx.x;
    const int tid = threadIdx.x;

    if (bx < PROD_CTAS) {
        // ================= PRODUCER =================
        int mtile, bcol;
        if (bx < 16) { mtile = 16 + (bx >> 3); bcol = (bx & 7) * 64; }
        else         { int q = bx - 16; mtile = q >> 3; bcol = (q & 7) * 64; }
        const int browg = mtile * 64;
        const bool isWs = (mtile >= 16);

        float* __restrict__ C = (!isWs)
            ? (d_gt + (size_t)browg * H_DIM)
            : (d_gs + (size_t)(browg - T_DIM) * H_DIM);

        __nv_bfloat16* smem = (__nv_bfloat16*)sbuf;
        const uint32_t smem_u32 = (uint32_t)__cvta_generic_to_shared(smem);

        const int wid  = tid >> 5;
        const int lane = tid & 31;
        const int wm   = wid & 1;
        const int wn   = wid >> 1;

        float acc[2][2][4];
        #pragma unroll
        for (int i = 0; i < 2; i++)
            #pragma unroll
            for (int j = 0; j < 2; j++)
                #pragma unroll
                for (int q = 0; q < 4; q++) acc[i][j][q] = 0.f;

        // staging: tid<128 -> A rows, tid>=128 -> B rows; 32 bf16 each
        const int isB   = tid >> 7;
        const int t128  = tid & 127;
        const int srow  = t128 >> 1;
        const int shalf = (t128 & 1) * 32;

        const float* fsrc;
        if (!isB) {
            int row = browg + srow;
            fsrc = (row < T_DIM) ? (text + (size_t)row * H_DIM)
                                 : (sstruct + (size_t)(row - T_DIM) * H_DIM);
        } else {
            fsrc = gate_w + (size_t)(bcol + srow) * 1024 + (isWs ? 512 : 0);
        }
        __nv_bfloat16* srowp = smem + (isB ? A_ELEMS : 0)
                                    + srow * LDS_STRIDE + shalf;

        // preload chunk 0 (off = 0, hi section)
        float4 v[8];
        #pragma unroll
        for (int q = 0; q < 8; q++)
            v[q] = *(const float4*)(fsrc + shalf + q * 4);

        const int arow_l = (lane & 7) + ((lane >> 3) & 1) * 8;
        const int ak_l   = (lane >> 4) * 8;
        const int brow_l = lane & 7;
        const int bk_l   = ((lane >> 3) & 1) * 8;
        const uint32_t Abase = smem_u32;
        const uint32_t Bbase = smem_u32 + A_ELEMS * 2;

        for (int c = 0; c < NCHUNKS; c++) {
            if (c > 0) __syncthreads();     // prior mma done reading smem

            // convert + store current chunk
            {
                const int off = isB ? chunk_off_W(c) : chunk_off_A(c);
                const bool lo = (off >= 512);
                uint4 st[4];
                #pragma unroll
                for (int q = 0; q < 4; q++) {
                    float4 a = v[2 * q], b = v[2 * q + 1];
                    if (lo) {
                        a.x = bflo(a.x); a.y = bflo(a.y);
                        a.z = bflo(a.z); a.w = bflo(a.w);
                        b.x = bflo(b.x); b.y = bflo(b.y);
                        b.z = bflo(b.z); b.w = bflo(b.w);
                    }
                    st[q].x = bfpack2(a.x, a.y);
                    st[q].y = bfpack2(a.z, a.w);
                    st[q].z = bfpack2(b.x, b.y);
                    st[q].w = bfpack2(b.z, b.w);
                }
                #pragma unroll
                for (int q = 0; q < 4; q++)
                    ((uint4*)srowp)[q] = st[q];
            }
            __syncthreads();                // staging visible

            // preload next chunk (overlaps mma)
            if (c + 1 < NCHUNKS) {
                const int off = isB ? chunk_off_W(c + 1) : chunk_off_A(c + 1);
                const int f32col = ((off >= 512) ? off - 512 : off) + shalf;
                #pragma unroll
                for (int q = 0; q < 8; q++)
                    v[q] = *(const float4*)(fsrc + f32col + q * 4);
            }

            // mma on staged chunk
            #pragma unroll
            for (int ks = 0; ks < KCHUNK; ks += 16) {
                uint32_t afr[2][4];
                #pragma unroll
                for (int mi = 0; mi < 2; mi++) {
                    const int rb = wm * 32 + mi * 16;
                    uint32_t addr = Abase +
                        ((rb + arow_l) * LDS_STRIDE + ks + ak_l) * 2;
                    asm volatile(
                        "ldmatrix.sync.aligned.m8n8.x4.shared.b16 {%0,%1,%2,%3}, [%4];"
                        : "=r"(afr[mi][0]), "=r"(afr[mi][1]),
                          "=r"(afr[mi][2]), "=r"(afr[mi][3])
                        : "r"(addr));
                }
                #pragma unroll
                for (int ni = 0; ni < 2; ni++) {
                    const int nb = wn * 16 + ni * 8;
                    uint32_t baddr = Bbase +
                        ((nb + brow_l) * LDS_STRIDE + ks + bk_l) * 2;
                    uint32_t b0, b1;
                    asm volatile(
                        "ldmatrix.sync.aligned.m8n8.x2.shared.b16 {%0,%1}, [%2];"
                        : "=r"(b0), "=r"(b1) : "r"(baddr));
                    #pragma unroll
                    for (int mi = 0; mi < 2; mi++) {
                        asm volatile(
                            "mma.sync.aligned.m16n8k16.row.col.f32.bf16.bf16.f32 "
                            "{%0,%1,%2,%3}, {%4,%5,%6,%7}, {%8,%9}, {%0,%1,%2,%3};"
                            : "+f"(acc[mi][ni][0]), "+f"(acc[mi][ni][1]),
                              "+f"(acc[mi][ni][2]), "+f"(acc[mi][ni][3])
                            : "r"(afr[mi][0]), "r"(afr[mi][1]),
                              "r"(afr[mi][2]), "r"(afr[mi][3]),
                              "r"(b0), "r"(b1));
                    }
                }
            }
        }

        const int frow = lane >> 2;
        const int fk   = (lane & 3) * 2;
        #pragma unroll
        for (int mi = 0; mi < 2; mi++) {
            const int row = wm * 32 + mi * 16 + frow;
            #pragma unroll
            for (int ni = 0; ni < 2; ni++) {
                const int col = bcol + wn * 16 + ni * 8 + fk;
                *(float2*)(C + (size_t)row * H_DIM + col) =
                    make_float2(acc[mi][ni][0], acc[mi][ni][1]);
                *(float2*)(C + (size_t)(row + 8) * H_DIM + col) =
                    make_float2(acc[mi][ni][2], acc[mi][ni][3]);
            }
        }

        __threadfence();
        __syncthreads();
        if (tid == 0) red_release_add(&d_cnt[mtile], 1u);

    } else if (bx < PROD_CTAS + CONS_CTAS) {
        // ================= CONSUMER =================
        const int cid   = bx - PROD_CTAS;
        const int ttile = cid >> 4;
        const int hc    = cid & 15;
        const int t0    = ttile * TT;
        const int h0    = hc * HC;

        float (*gs_s)[HC] = (float (*)[HC])sbuf;
        float (*st_s)[HC] = (float (*)[HC])(sbuf + S_DIM * HC * 4);

        const int hx = tid & 7;
        const int ts = tid >> 3;
        const int h  = h0 + hx * 4;
        const int r  = t0 + ts;

        #pragma unroll
        for (int i = tid; i < S_DIM * (HC / 4); i += 256) {
            int s  = i >> 3;
            int c4 = (i & 7) * 4;
            *(float4*)&st_s[s][c4] =
                *(const float4*)(sstruct + (size_t)s * H_DIM + h0 + c4);
        }

        const int* __restrict__ mp = mask + (size_t)r * S_DIM;
        float* __restrict__ gp = gates + (size_t)r * S_DIM * H_DIM + h;

        // zero-pass: masked-0 gates need nothing from the GEMM
        const float4 z4 = make_float4(0.f, 0.f, 0.f, 0.f);
        #pragma unroll 4
        for (int s = 0; s < S_DIM; s++) {
            if (mp[s] == 0) __stcs((float4*)(gp + (size_t)s * H_DIM), z4);
        }

        const int gtile = ttile >> 1;
        if (tid == 0) {
            while (ld_acq(&d_cnt[16]) < 8u)    __nanosleep(64);
            while (ld_acq(&d_cnt[17]) < 8u)    __nanosleep(64);
            while (ld_acq(&d_cnt[gtile]) < 8u) __nanosleep(64);
        }
        __syncthreads();

        #pragma unroll
        for (int i = tid; i < S_DIM * (HC / 4); i += 256) {
            int s  = i >> 3;
            int c4 = (i & 7) * 4;
            *(float4*)&gs_s[s][c4] =
                *(const float4*)(d_gs + (size_t)s * H_DIM + h0 + c4);
        }
        __syncthreads();

        const float4 bias = *(const float4*)(gate_b + h);
        float4 gtb;
        {
            float4 a = *(const float4*)(d_gt + (size_t)r * H_DIM + h);
            gtb = make_float4(a.x + bias.x, a.y + bias.y, a.z + bias.z, a.w + bias.w);
        }
        float4 acc = make_float4(0.f, 0.f, 0.f, 0.f);

        #pragma unroll 4
        for (int s = 0; s < S_DIM; s++) {
            if (mp[s] != 0) {
                const float4 gs4 = *(const float4*)&gs_s[s][hx * 4];
                const float4 sv4 = *(const float4*)&st_s[s][hx * 4];
                float4 g;
                g.x = fmaxf(gtb.x + gs4.x, 0.f);
                g.y = fmaxf(gtb.y + gs4.y, 0.f);
                g.z = fmaxf(gtb.z + gs4.z, 0.f);
                g.w = fmaxf(gtb.w + gs4.w, 0.f);
                __stcs((float4*)(gp + (size_t)s * H_DIM), g);
                acc.x = fmaf(g.x, sv4.x, acc.x);
                acc.y = fmaf(g.y, sv4.y, acc.y);
                acc.z = fmaf(g.z, sv4.z, acc.z);
                acc.w = fmaf(g.w, sv4.w, acc.w);
            }
        }

        {
            float4 t4 = *(const float4*)(text + (size_t)r * H_DIM + h);
            *(float4*)(d_x + (size_t)r * H_DIM + h) =
                make_float4(t4.x + acc.x, t4.y + acc.y, t4.z + acc.z, t4.w + acc.w);
        }
        __threadfence();
        __syncthreads();
        if (tid == 0) red_release_add(&d_tcnt[ttile], 1u);

    } else {
        // ================= LAYERNORM (tail) =================
        const int cid = bx - (PROD_CTAS + CONS_CTAS);   // 0..511
        const int tg  = tid >> 7;
        const int h4  = tid & 127;
        const int h   = h4 * 4;
        const int r   = cid * 2 + tg;
        const int tt  = cid >> 4;                       // (cid*2)>>5

        if (tid == 0) {
            while (ld_acq(&d_tcnt[tt]) < 16u) __nanosleep(128);
        }
        __syncthreads();

        float4 v = *(const float4*)(d_x + (size_t)r * H_DIM + h);
        float s1 = v.x + v.y + v.z + v.w;
        float s2 = v.x * v.x + v.y * v.y + v.z * v.z + v.w * v.w;

        const int lane = tid & 31;
        const int wg   = (tid >> 5) & 3;
        #pragma unroll
        for (int o = 16; o > 0; o >>= 1) {
            s1 += __shfl_xor_sync(0xFFFFFFFFu, s1, o);
            s2 += __shfl_xor_sync(0xFFFFFFFFu, s2, o);
        }
        if (lane == 0) { lnred[0][tg][wg] = s1; lnred[1][tg][wg] = s2; }
        __syncthreads();

        s1 = lnred[0][tg][0] + lnred[0][tg][1] + lnred[0][tg][2] + lnred[0][tg][3];
        s2 = lnred[1][tg][0] + lnred[1][tg][1] + lnred[1][tg][2] + lnred[1][tg][3];
        float mu  = s1 * (1.f / H_DIM);
        float var = s2 * (1.f / H_DIM) - mu * mu;
        float inv = rsqrtf(var + LN_EPS);

        const float4 gm = *(const float4*)(gamma + h);
        const float4 bt = *(const float4*)(beta  + h);
        float4 o;
        o.x = (v.x - mu) * inv * gm.x + bt.x;
        o.y = (v.y - mu) * inv * gm.y + bt.y;
        o.z = (v.z - mu) * inv * gm.z + bt.z;
        o.w = (v.w - mu) * inv * gm.w + bt.w;
        *(float4*)(enriched + (size_t)r * H_DIM + h) = o;
    }
}

// ---------------------------------------------------------------------------
extern "C" void kernel_launch(void* const* d_in, const int* in_sizes, int n_in,
                              void* d_out, int out_size)
{
    const float* text    = (const float*)d_in[0];
    const float* sstruct = (const float*)d_in[1];
    const int*   mask    = (const int*)  d_in[2];
    const float* gate_w  = (const float*)d_in[3];
    const float* gate_b  = (const float*)d_in[4];
    const float* gamma   = (const float*)d_in[5];
    const float* beta    = (const float*)d_in[6];

    float* enriched = (float*)d_out;
    float* gates    = (float*)d_out + (size_t)T_DIM * H_DIM;

    merged_kernel<<<PROD_CTAS + CONS_CTAS + LN_CTAS, 256>>>(
        text, sstruct, mask, gate_w, gate_b, gamma, beta,
        enriched, gates);
}